// round 12
// baseline (speedup 1.0000x reference)
#include <cuda_runtime.h>
#include <cstdint>

#define THREADS   256
#define FDIM      64
#define EDIM      32
#define ROWBYTES  64                  // 32 bf16, XOR-swizzled 16B chunks (no pad)
#define BUFBYTES  (FDIM * ROWBYTES)   // 4096 B per [64][32] bf16 buffer
#define NBUF      12                  // 0..9 = head*2+{h,l} of y; 10 = xh; 11 = xl
#define SMEM_BYTES (NBUF * BUFBYTES)  // 49152

static __device__ __forceinline__ float ex2f(float x) {
    float r;
    asm("ex2.approx.ftz.f32 %0, %1;" : "=f"(r) : "f"(x));
    return r;
}
static __device__ __forceinline__ uint32_t pack_bf16x2(float hi, float lo) {
    uint32_t r;
    asm("cvt.rn.bf16x2.f32 %0, %1, %2;" : "=r"(r) : "f"(hi), "f"(lo));
    return r;
}
static __device__ __forceinline__ void ldsm4(uint32_t* r, uint32_t addr) {
    asm volatile("ldmatrix.sync.aligned.m8n8.x4.shared.b16 {%0,%1,%2,%3}, [%4];"
                 : "=r"(r[0]), "=r"(r[1]), "=r"(r[2]), "=r"(r[3]) : "r"(addr));
}
static __device__ __forceinline__ void mma16816(float* d, const uint32_t* a,
                                                uint32_t b0, uint32_t b1) {
    asm volatile("mma.sync.aligned.m16n8k16.row.col.f32.bf16.bf16.f32 "
                 "{%0,%1,%2,%3}, {%4,%5,%6,%7}, {%8,%9}, {%0,%1,%2,%3};"
                 : "+f"(d[0]), "+f"(d[1]), "+f"(d[2]), "+f"(d[3])
                 : "r"(a[0]), "r"(a[1]), "r"(a[2]), "r"(a[3]), "r"(b0), "r"(b1));
}
static __device__ __forceinline__ void mma16816_zc(float* d, const uint32_t* a,
                                                   uint32_t b0, uint32_t b1) {
    asm volatile("mma.sync.aligned.m16n8k16.row.col.f32.bf16.bf16.f32 "
                 "{%0,%1,%2,%3}, {%4,%5,%6,%7}, {%8,%9}, {%10,%10,%10,%10};"
                 : "=f"(d[0]), "=f"(d[1]), "=f"(d[2]), "=f"(d[3])
                 : "r"(a[0]), "r"(a[1]), "r"(a[2]), "r"(a[3]), "r"(b0), "r"(b1),
                   "f"(0.0f));
}

__global__ void __launch_bounds__(THREADS, 2)
afm_kernel(const float* __restrict__ x,
           const float* __restrict__ attn_w,
           const float* __restrict__ attn_b,
           const float* __restrict__ attn_h,
           const float* __restrict__ pool_w,
           const float* __restrict__ pool_b,
           float* __restrict__ out)
{
    extern __shared__ __align__(16) char sm[];
    __shared__ float w5[EDIM][8];
    __shared__ float rse[8], rsq[8];

    const int t = threadIdx.x;
    const int b = blockIdx.x;
    const float* xb = x + (size_t)b * (FDIM * EDIM);

    // ======= prologue: 256 threads, each splits 8 e-values of one f-row ======
    const int f = t >> 2;             // feature row 0..63
    const int q = t & 3;              // chunk of 8 e (coalesced LDG)
    const float* src = xb + f * EDIM + q * 8;
    float4 va = reinterpret_cast<const float4*>(src)[0];
    float4 vb = reinterpret_cast<const float4*>(src)[1];

    if (t < EDIM) {
        float4 wv = reinterpret_cast<const float4*>(attn_w)[t];
        w5[t][0] = wv.x; w5[t][1] = wv.y; w5[t][2] = wv.z; w5[t][3] = wv.w;
        w5[t][4] = pool_w[t];
    }
    __syncthreads();

    float v[8] = { va.x, va.y, va.z, va.w, vb.x, vb.y, vb.z, vb.w };

    {
        uint32_t xh4[4], xl4[4], yh4[5][4], yl4[5][4];
        #pragma unroll
        for (int p = 0; p < 4; p++) {
            int e = q * 8 + p * 2;
            float a0 = v[p * 2], a1 = v[p * 2 + 1];
            uint32_t u0 = __float_as_uint(a0), u1 = __float_as_uint(a1);
            xh4[p] = __byte_perm(u0, u1, 0x7632);
            float t0 = a0 - __uint_as_float(u0 & 0xFFFF0000u);
            float t1 = a1 - __uint_as_float(u1 & 0xFFFF0000u);
            xl4[p] = pack_bf16x2(t1, t0);
            float4 wr0 = *reinterpret_cast<const float4*>(&w5[e][0]);
            float4 wr1 = *reinterpret_cast<const float4*>(&w5[e + 1][0]);
            float wa0[5] = { wr0.x, wr0.y, wr0.z, wr0.w, w5[e][4] };
            float wa1[5] = { wr1.x, wr1.y, wr1.z, wr1.w, w5[e + 1][4] };
            #pragma unroll
            for (int a = 0; a < 5; a++) {
                float y0 = a0 * wa0[a], y1 = a1 * wa1[a];
                uint32_t q0 = __float_as_uint(y0), q1 = __float_as_uint(y1);
                yh4[a][p] = __byte_perm(q0, q1, 0x7632);
                float g0 = y0 - __uint_as_float(q0 & 0xFFFF0000u);
                float g1 = y1 - __uint_as_float(q1 & 0xFFFF0000u);
                yl4[a][p] = pack_bf16x2(g1, g0);
            }
        }
        const int fs = (f >> 1) & 3;
        int off = f * ROWBYTES + ((q ^ fs) << 4);
        *reinterpret_cast<uint4*>(sm + 10 * BUFBYTES + off) = *reinterpret_cast<uint4*>(xh4);
        *reinterpret_cast<uint4*>(sm + 11 * BUFBYTES + off) = *reinterpret_cast<uint4*>(xl4);
        #pragma unroll
        for (int a = 0; a < 5; a++) {
            *reinterpret_cast<uint4*>(sm + (2 * a + 0) * BUFBYTES + off) = *reinterpret_cast<uint4*>(yh4[a]);
            *reinterpret_cast<uint4*>(sm + (2 * a + 1) * BUFBYTES + off) = *reinterpret_cast<uint4*>(yl4[a]);
        }
    }
    __syncthreads();

    // ====== mainloop: 8 warps, one ti per warp, 2-3 j-tiles each =============
    const int lane = t & 31;
    const int w    = t >> 5;
    const int lg = lane >> 3, lr = lane & 7;
    const int ls = (lr >> 1) & 3;

    const uint32_t a_row   = (uint32_t)(((lg & 1) * 8 + lr) * ROWBYTES);
    const uint32_t a_csel0 = (uint32_t)((((lg >> 1)    ) ^ ls) << 4);
    const uint32_t a_csel1 = (uint32_t)((((lg >> 1) | 2) ^ ls) << 4);
    const uint32_t b_off   = (uint32_t)((lr * ROWBYTES) + ((lg ^ ls) << 4));

    uint32_t smb = (uint32_t)__cvta_generic_to_shared(sm);
    const uint32_t b_base = smb + b_off;

    // bias folded into relu threshold; log2e folded into h (base-2 exp);
    // constant sum(b*h) cancels in the softmax ratio.
    const float nb[4] = { -attn_b[0], -attn_b[1], -attn_b[2], -attn_b[3] };
    const float L2E = 1.4426950408889634f;
    const float ha[4] = { attn_h[0] * L2E, attn_h[1] * L2E,
                          attn_h[2] * L2E, attn_h[3] * L2E };

    // warp -> (ti; tj list). Every warp has a single ti.
    const int TI_[8]  = {0,0,0,1,1,2,2,3};
    const int TJ0_[8] = {0,3,6,2,5,4,6,6};
    const int TJ1_[8] = {1,4,7,3,6,5,7,7};
    const int TJ2_[8] = {2,5,0,4,7,0,0,0};      // valid only where HAS3
    const bool HAS3 = (w == 0) | (w == 1) | (w == 3) | (w == 4);
    const bool DIAG = (w == 0) | (w == 3) | (w == 5) | (w == 7);  // k0,k1 masked

    const int ti  = TI_[w];
    const int ir0 = (lane >> 2);
    const int jc0 = 2 * (lane & 3);

    // A-fragments: loaded exactly once per warp
    uint32_t ah0[4], ah1[4], al0[4], al1[4];
    {
        const uint32_t tio = (uint32_t)(ti * 16 * ROWBYTES);
        ldsm4(ah0, smb + 10 * BUFBYTES + a_row + a_csel0 + tio);
        ldsm4(ah1, smb + 10 * BUFBYTES + a_row + a_csel1 + tio);
        ldsm4(al0, smb + 11 * BUFBYTES + a_row + a_csel0 + tio);
        ldsm4(al1, smb + 11 * BUFBYTES + a_row + a_csel1 + tio);
    }

    float ose = 0.f, osq = 0.f;

    auto do_tile = [&](int tj, bool domask) {
        const uint32_t brow = b_base + (uint32_t)(tj * 8 * ROWBYTES);
        float tsc[4], qv[4];
        #pragma unroll
        for (int a = 0; a < 5; a++) {
            uint32_t bh[4], bl[4];
            ldsm4(bh, brow + (uint32_t)((2 * a + 0) * BUFBYTES));
            ldsm4(bl, brow + (uint32_t)((2 * a + 1) * BUFBYTES));

            float d[4];
            mma16816_zc(d, ah0, bh[0], bh[1]);
            mma16816(d, ah1, bh[2], bh[3]);
            mma16816(d, ah0, bl[0], bl[1]);
            mma16816(d, ah1, bl[2], bl[3]);
            mma16816(d, al0, bh[0], bh[1]);
            mma16816(d, al1, bh[2], bh[3]);

            if (a == 0) {
                #pragma unroll
                for (int cc = 0; cc < 4; cc++) tsc[cc] = fmaxf(d[cc], nb[0]) * ha[0];
            } else if (a < 4) {
                #pragma unroll
                for (int cc = 0; cc < 4; cc++) tsc[cc] += fmaxf(d[cc], nb[a]) * ha[a];
            } else {
                #pragma unroll
                for (int cc = 0; cc < 4; cc++) qv[cc] = d[cc];
            }
        }

        if (domask) {
            const int ib = ti * 16 + ir0, jb = tj * 8 + jc0;
            #pragma unroll
            for (int cc = 0; cc < 4; cc++) {
                int i = ib + ((cc >= 2) ? 8 : 0);
                int j = jb + (cc & 1);
                if (i >= j) tsc[cc] = -1e30f;    // ex2 -> 0
            }
        }
        float e0 = ex2f(tsc[0]), e1 = ex2f(tsc[1]);
        float e2 = ex2f(tsc[2]), e3 = ex2f(tsc[3]);
        ose += (e0 + e1) + (e2 + e3);
        osq += (e0 * qv[0] + e1 * qv[1]) + (e2 * qv[2] + e3 * qv[3]);
    };

    do_tile(TJ0_[w], DIAG);
    do_tile(TJ1_[w], DIAG);
    if (HAS3) do_tile(TJ2_[w], false);

    // ================= reduce: plain sums (no max needed) ====================
    #pragma unroll
    for (int o = 16; o; o >>= 1) {
        ose += __shfl_xor_sync(0xffffffffu, ose, o);
        osq += __shfl_xor_sync(0xffffffffu, osq, o);
    }
    if (lane == 0) { rse[w] = ose; rsq[w] = osq; }
    __syncthreads();
    if (t == 0) {
        float S = 0.f, Q = 0.f;
        #pragma unroll
        for (int i = 0; i < 8; i++) { S += rse[i]; Q += rsq[i]; }
        out[b] = Q / S + pool_b[0];
    }
}

extern "C" void kernel_launch(void* const* d_in, const int* in_sizes, int n_in,
                              void* d_out, int out_size)
{
    const float* x      = (const float*)d_in[0];
    const float* attn_w = (const float*)d_in[1];
    const float* attn_b = (const float*)d_in[2];
    const float* attn_h = (const float*)d_in[3];
    const float* pool_w = (const float*)d_in[4];
    const float* pool_b = (const float*)d_in[5];
    float* out = (float*)d_out;

    cudaFuncSetAttribute(afm_kernel, cudaFuncAttributeMaxDynamicSharedMemorySize, SMEM_BYTES);

    int B = in_sizes[0] / (FDIM * EDIM);
    afm_kernel<<<B, THREADS, SMEM_BYTES>>>(x, attn_w, attn_b, attn_h, pool_w, pool_b, out);
}

// round 13
// speedup vs baseline: 1.1989x; 1.1989x over previous
#include <cuda_runtime.h>
#include <cstdint>

#define THREADS   128
#define FDIM      64
#define EDIM      32
#define ROWBYTES  64                  // 32 bf16, XOR-swizzled 16B chunks (no pad)
#define BUFBYTES  (FDIM * ROWBYTES)   // 4096 B per [64][32] bf16 buffer
#define NBUF      12                  // 0..9 = head*2+{h,l} of y; 10 = xh; 11 = xl
#define SMEM_BYTES (NBUF * BUFBYTES)  // 49152

static __device__ __forceinline__ float ex2f(float x) {
    float r;
    asm("ex2.approx.ftz.f32 %0, %1;" : "=f"(r) : "f"(x));
    return r;
}
static __device__ __forceinline__ uint32_t pack_bf16x2(float hi, float lo) {
    uint32_t r;
    asm("cvt.rn.bf16x2.f32 %0, %1, %2;" : "=r"(r) : "f"(hi), "f"(lo));
    return r;
}
static __device__ __forceinline__ void ldsm4(uint32_t* r, uint32_t addr) {
    asm volatile("ldmatrix.sync.aligned.m8n8.x4.shared.b16 {%0,%1,%2,%3}, [%4];"
                 : "=r"(r[0]), "=r"(r[1]), "=r"(r[2]), "=r"(r[3]) : "r"(addr));
}
static __device__ __forceinline__ void mma16816(float* d, const uint32_t* a,
                                                uint32_t b0, uint32_t b1) {
    asm volatile("mma.sync.aligned.m16n8k16.row.col.f32.bf16.bf16.f32 "
                 "{%0,%1,%2,%3}, {%4,%5,%6,%7}, {%8,%9}, {%0,%1,%2,%3};"
                 : "+f"(d[0]), "+f"(d[1]), "+f"(d[2]), "+f"(d[3])
                 : "r"(a[0]), "r"(a[1]), "r"(a[2]), "r"(a[3]), "r"(b0), "r"(b1));
}
static __device__ __forceinline__ void mma16816_zc(float* d, const uint32_t* a,
                                                   uint32_t b0, uint32_t b1) {
    asm volatile("mma.sync.aligned.m16n8k16.row.col.f32.bf16.bf16.f32 "
                 "{%0,%1,%2,%3}, {%4,%5,%6,%7}, {%8,%9}, {%10,%10,%10,%10};"
                 : "=f"(d[0]), "=f"(d[1]), "=f"(d[2]), "=f"(d[3])
                 : "r"(a[0]), "r"(a[1]), "r"(a[2]), "r"(a[3]), "r"(b0), "r"(b1),
                   "f"(0.0f));
}

__global__ void __launch_bounds__(THREADS, 4)
afm_kernel(const float* __restrict__ x,
           const float* __restrict__ attn_w,
           const float* __restrict__ attn_b,
           const float* __restrict__ attn_h,
           const float* __restrict__ pool_w,
           const float* __restrict__ pool_b,
           float* __restrict__ out)
{
    extern __shared__ __align__(16) char sm[];
    __shared__ float w5[EDIM][8];
    __shared__ float rse[4], rsq[4];

    const int t = threadIdx.x;
    const int b = blockIdx.x;
    const float* xb = x + (size_t)b * (FDIM * EDIM);

    // ================= prologue: split x, build 5 y-tables (bf16 hi/lo) ======
    const int f = t & 63;
    const int h = t >> 6;             // e-half
    const float* src = xb + f * EDIM + h * 16;
    float4 v4[4];
    #pragma unroll
    for (int q = 0; q < 4; q++) v4[q] = reinterpret_cast<const float4*>(src)[q];

    if (t < EDIM) {
        float4 wv = reinterpret_cast<const float4*>(attn_w)[t];
        w5[t][0] = wv.x; w5[t][1] = wv.y; w5[t][2] = wv.z; w5[t][3] = wv.w;
        w5[t][4] = pool_w[t];
    }
    __syncthreads();

    float v[16];
    #pragma unroll
    for (int q = 0; q < 4; q++) {
        v[q * 4 + 0] = v4[q].x; v[q * 4 + 1] = v4[q].y;
        v[q * 4 + 2] = v4[q].z; v[q * 4 + 3] = v4[q].w;
    }

    const int fs = (f >> 1) & 3;      // row swizzle term
    #pragma unroll
    for (int c = 0; c < 2; c++) {     // chunk of 8 e (one uint4)
        uint32_t xh4[4], xl4[4], yh4[5][4], yl4[5][4];
        #pragma unroll
        for (int p = 0; p < 4; p++) {
            int ei = c * 8 + p * 2;
            int e  = h * 16 + ei;
            float a0 = v[ei], a1 = v[ei + 1];
            uint32_t u0 = __float_as_uint(a0), u1 = __float_as_uint(a1);
            xh4[p] = __byte_perm(u0, u1, 0x7632);
            float t0 = a0 - __uint_as_float(u0 & 0xFFFF0000u);
            float t1 = a1 - __uint_as_float(u1 & 0xFFFF0000u);
            xl4[p] = pack_bf16x2(t1, t0);
            float4 wr0 = *reinterpret_cast<const float4*>(&w5[e][0]);
            float4 wr1 = *reinterpret_cast<const float4*>(&w5[e + 1][0]);
            float wa0[5] = { wr0.x, wr0.y, wr0.z, wr0.w, w5[e][4] };
            float wa1[5] = { wr1.x, wr1.y, wr1.z, wr1.w, w5[e + 1][4] };
            #pragma unroll
            for (int a = 0; a < 5; a++) {
                float y0 = a0 * wa0[a], y1 = a1 * wa1[a];
                uint32_t q0 = __float_as_uint(y0), q1 = __float_as_uint(y1);
                yh4[a][p] = __byte_perm(q0, q1, 0x7632);
                float g0 = y0 - __uint_as_float(q0 & 0xFFFF0000u);
                float g1 = y1 - __uint_as_float(q1 & 0xFFFF0000u);
                yl4[a][p] = pack_bf16x2(g1, g0);
            }
        }
        int off = f * ROWBYTES + (((h * 2 + c) ^ fs) << 4);
        *reinterpret_cast<uint4*>(sm + 10 * BUFBYTES + off) = *reinterpret_cast<uint4*>(xh4);
        *reinterpret_cast<uint4*>(sm + 11 * BUFBYTES + off) = *reinterpret_cast<uint4*>(xl4);
        #pragma unroll
        for (int a = 0; a < 5; a++) {
            *reinterpret_cast<uint4*>(sm + (2 * a + 0) * BUFBYTES + off) = *reinterpret_cast<uint4*>(yh4[a]);
            *reinterpret_cast<uint4*>(sm + (2 * a + 1) * BUFBYTES + off) = *reinterpret_cast<uint4*>(yl4[a]);
        }
    }
    __syncthreads();

    // ====== mainloop: A = x (i side), B = y_a (j side) =======================
    const int lane = t & 31;
    const int w    = t >> 5;
    const int lg = lane >> 3, lr = lane & 7;
    const int ls = (lr >> 1) & 3;

    const uint32_t a_row   = (uint32_t)(((lg & 1) * 8 + lr) * ROWBYTES);
    const uint32_t a_csel0 = (uint32_t)((((lg >> 1)    ) ^ ls) << 4);   // e 0..15
    const uint32_t a_csel1 = (uint32_t)((((lg >> 1) | 2) ^ ls) << 4);   // e 16..31
    const uint32_t b_off   = (uint32_t)((lr * ROWBYTES) + ((lg ^ ls) << 4));

    uint32_t smb = (uint32_t)__cvta_generic_to_shared(sm);
    const uint32_t xh0 = smb + 10 * BUFBYTES + a_row + a_csel0;
    const uint32_t xh1 = smb + 10 * BUFBYTES + a_row + a_csel1;
    const uint32_t xl0 = smb + 11 * BUFBYTES + a_row + a_csel0;
    const uint32_t xl1 = smb + 11 * BUFBYTES + a_row + a_csel1;
    const uint32_t b_base = smb + b_off;

    // bias folded into relu threshold: relu(d+b)*h = max(d,-b)*h + b*h;
    // constant sum(b*h) cancels under softmax. log2e folded into h -> exp2.
    const float nb[4] = { -attn_b[0], -attn_b[1], -attn_b[2], -attn_b[3] };
    const float L2E = 1.4426950408889634f;
    const float ha[4] = { attn_h[0] * L2E, attn_h[1] * L2E,
                          attn_h[2] * L2E, attn_h[3] * L2E };

    const int TI4[4][5] = {{0,0,0,0,0},{0,0,0,1,1},{1,1,1,1,2},{2,2,2,3,3}};
    const int TJ4[4][5] = {{0,1,2,3,4},{5,6,7,2,3},{4,5,6,7,4},{5,6,7,6,7}};
    const int DIAGMASK[4] = { 0x03, 0x18, 0x10, 0x19 };   // diagonal-touching tiles

    const int ir0 = (lane >> 2);
    const int jc0 = 2 * (lane & 3);

    uint32_t ah0[4], ah1[4], al0[4], al1[4];
    int prev_ti = -1;

    float ose = 0.f, osq = 0.f;     // unnormalized sums (no running max needed)
    const int dmask = DIAGMASK[w];

    #pragma unroll
    for (int k = 0; k < 5; k++) {
        const int ti = TI4[w][k], tj = TJ4[w][k];

        if (ti != prev_ti) {
            const uint32_t tio = (uint32_t)(ti * 16 * ROWBYTES);
            ldsm4(ah0, xh0 + tio);
            ldsm4(ah1, xh1 + tio);
            ldsm4(al0, xl0 + tio);
            ldsm4(al1, xl1 + tio);
            prev_ti = ti;
        }

        const uint32_t brow = b_base + (uint32_t)(tj * 8 * ROWBYTES);

        float tsc[4];
        float qv[4];
        #pragma unroll
        for (int a = 0; a < 5; a++) {
            uint32_t bh[4], bl[4];
            ldsm4(bh, brow + (uint32_t)((2 * a + 0) * BUFBYTES));
            ldsm4(bl, brow + (uint32_t)((2 * a + 1) * BUFBYTES));

            float d[4];
            mma16816_zc(d, ah0, bh[0], bh[1]);  // xh·yh k0 (zero C -> RZ)
            mma16816(d, ah1, bh[2], bh[3]);     // xh·yh k1
            mma16816(d, ah0, bl[0], bl[1]);     // xh·yl k0
            mma16816(d, ah1, bl[2], bl[3]);     // xh·yl k1
            mma16816(d, al0, bh[0], bh[1]);     // xl·yh k0
            mma16816(d, al1, bh[2], bh[3]);     // xl·yh k1

            if (a == 0) {
                #pragma unroll
                for (int cc = 0; cc < 4; cc++)
                    tsc[cc] = fmaxf(d[cc], nb[0]) * ha[0];
            } else if (a < 4) {
                #pragma unroll
                for (int cc = 0; cc < 4; cc++)
                    tsc[cc] += fmaxf(d[cc], nb[a]) * ha[a];
            } else {
                #pragma unroll
                for (int cc = 0; cc < 4; cc++) qv[cc] = d[cc];
            }
        }

        // mask only diagonal-touching tiles (warp-uniform branch); ex2(-1e30)=0
        if ((dmask >> k) & 1) {
            const int ib = ti * 16 + ir0, jb = tj * 8 + jc0;
            #pragma unroll
            for (int cc = 0; cc < 4; cc++) {
                int i = ib + ((cc >= 2) ? 8 : 0);
                int j = jb + (cc & 1);
                if (i >= j) tsc[cc] = -1e30f;
            }
        }

        float e0 = ex2f(tsc[0]), e1 = ex2f(tsc[1]);
        float e2 = ex2f(tsc[2]), e3 = ex2f(tsc[3]);
        ose += (e0 + e1) + (e2 + e3);
        osq += (e0 * qv[0] + e1 * qv[1]) + (e2 * qv[2] + e3 * qv[3]);
    }

    // ================= reduce: plain sums ====================================
    #pragma unroll
    for (int o = 16; o; o >>= 1) {
        ose += __shfl_xor_sync(0xffffffffu, ose, o);
        osq += __shfl_xor_sync(0xffffffffu, osq, o);
    }
    if (lane == 0) { rse[w] = ose; rsq[w] = osq; }
    __syncthreads();
    if (t == 0) {
        float S = rse[0] + rse[1] + rse[2] + rse[3];
        float Q = rsq[0] + rsq[1] + rsq[2] + rsq[3];
        out[b] = Q / S + pool_b[0];
    }
}

extern "C" void kernel_launch(void* const* d_in, const int* in_sizes, int n_in,
                              void* d_out, int out_size)
{
    const float* x      = (const float*)d_in[0];
    const float* attn_w = (const float*)d_in[1];
    const float* attn_b = (const float*)d_in[2];
    const float* attn_h = (const float*)d_in[3];
    const float* pool_w = (const float*)d_in[4];
    const float* pool_b = (const float*)d_in[5];
    float* out = (float*)d_out;

    cudaFuncSetAttribute(afm_kernel, cudaFuncAttributeMaxDynamicSharedMemorySize, SMEM_BYTES);

    int B = in_sizes[0] / (FDIM * EDIM);
    afm_kernel<<<B, THREADS, SMEM_BYTES>>>(x, attn_w, attn_b, attn_h, pool_w, pool_b, out);
}

// round 15
// speedup vs baseline: 1.2886x; 1.0748x over previous
#include <cuda_runtime.h>
#include <cstdint>

#define THREADS   128
#define FDIM      64
#define EDIM      32
#define ROWBYTES  64                  // 32 bf16, XOR-swizzled 16B chunks
#define BUFBYTES  (FDIM * ROWBYTES)   // 4096 B per [64][32] bf16 buffer
#define NBUF      12                  // 2a/2a+1 = yh/yl (a=0..4, 4=pool); 10=xh; 11=xl
#define SMEM_BYTES (NBUF * BUFBYTES)  // 49152

static __device__ __forceinline__ float ex2f(float x) {
    float r;
    asm("ex2.approx.ftz.f32 %0, %1;" : "=f"(r) : "f"(x));
    return r;
}
static __device__ __forceinline__ uint32_t pack_bf16x2(float hi, float lo) {
    uint32_t r;
    asm("cvt.rn.bf16x2.f32 %0, %1, %2;" : "=r"(r) : "f"(hi), "f"(lo));
    return r;
}
static __device__ __forceinline__ void ldsm4(uint32_t* r, uint32_t addr) {
    asm volatile("ldmatrix.sync.aligned.m8n8.x4.shared.b16 {%0,%1,%2,%3}, [%4];"
                 : "=r"(r[0]), "=r"(r[1]), "=r"(r[2]), "=r"(r[3]) : "r"(addr));
}
static __device__ __forceinline__ void mma16816(float* d, const uint32_t* a,
                                                uint32_t b0, uint32_t b1) {
    asm volatile("mma.sync.aligned.m16n8k16.row.col.f32.bf16.bf16.f32 "
                 "{%0,%1,%2,%3}, {%4,%5,%6,%7}, {%8,%9}, {%0,%1,%2,%3};"
                 : "+f"(d[0]), "+f"(d[1]), "+f"(d[2]), "+f"(d[3])
                 : "r"(a[0]), "r"(a[1]), "r"(a[2]), "r"(a[3]), "r"(b0), "r"(b1));
}
static __device__ __forceinline__ void mma16816_zc(float* d, const uint32_t* a,
                                                   uint32_t b0, uint32_t b1) {
    asm volatile("mma.sync.aligned.m16n8k16.row.col.f32.bf16.bf16.f32 "
                 "{%0,%1,%2,%3}, {%4,%5,%6,%7}, {%8,%9}, {%10,%10,%10,%10};"
                 : "=f"(d[0]), "=f"(d[1]), "=f"(d[2]), "=f"(d[3])
                 : "r"(a[0]), "r"(a[1]), "r"(a[2]), "r"(a[3]), "r"(b0), "r"(b1),
                   "f"(0.0f));
}

__global__ void __launch_bounds__(THREADS, 4)
afm_kernel(const float* __restrict__ x,
           const float* __restrict__ attn_w,
           const float* __restrict__ attn_b,
           const float* __restrict__ attn_h,
           const float* __restrict__ pool_w,
           const float* __restrict__ pool_b,
           float* __restrict__ out)
{
    extern __shared__ __align__(16) char sm[];
    __shared__ float w5[EDIM][8];
    __shared__ float rse[4], rsq[4];

    const int t = threadIdx.x;
    const int b = blockIdx.x;
    const float* xb = x + (size_t)b * (FDIM * EDIM);

    // ================= prologue: split x, build 5 y-tables (bf16 hi/lo) ======
    const int f = t & 63;
    const int h = t >> 6;             // e-half
    const float* src = xb + f * EDIM + h * 16;
    float4 v4[4];
    #pragma unroll
    for (int q = 0; q < 4; q++) v4[q] = reinterpret_cast<const float4*>(src)[q];

    if (t < EDIM) {
        float4 wv = reinterpret_cast<const float4*>(attn_w)[t];
        w5[t][0] = wv.x; w5[t][1] = wv.y; w5[t][2] = wv.z; w5[t][3] = wv.w;
        w5[t][4] = pool_w[t];
    }
    __syncthreads();

    float v[16];
    #pragma unroll
    for (int q = 0; q < 4; q++) {
        v[q * 4 + 0] = v4[q].x; v[q * 4 + 1] = v4[q].y;
        v[q * 4 + 2] = v4[q].z; v[q * 4 + 3] = v4[q].w;
    }

    const int fs = (f >> 1) & 3;      // row swizzle term
    #pragma unroll
    for (int c = 0; c < 2; c++) {     // chunk of 8 e (one uint4)
        uint32_t xh4[4], xl4[4], yh4[5][4], yl4[5][4];
        #pragma unroll
        for (int p = 0; p < 4; p++) {
            int ei = c * 8 + p * 2;
            int e  = h * 16 + ei;
            float a0 = v[ei], a1 = v[ei + 1];
            uint32_t u0 = __float_as_uint(a0), u1 = __float_as_uint(a1);
            xh4[p] = __byte_perm(u0, u1, 0x7632);
            float t0 = a0 - __uint_as_float(u0 & 0xFFFF0000u);
            float t1 = a1 - __uint_as_float(u1 & 0xFFFF0000u);
            xl4[p] = pack_bf16x2(t1, t0);
            float4 wr0 = *reinterpret_cast<const float4*>(&w5[e][0]);
            float4 wr1 = *reinterpret_cast<const float4*>(&w5[e + 1][0]);
            float wa0[5] = { wr0.x, wr0.y, wr0.z, wr0.w, w5[e][4] };
            float wa1[5] = { wr1.x, wr1.y, wr1.z, wr1.w, w5[e + 1][4] };
            #pragma unroll
            for (int a = 0; a < 5; a++) {
                float y0 = a0 * wa0[a], y1 = a1 * wa1[a];
                uint32_t q0 = __float_as_uint(y0), q1 = __float_as_uint(y1);
                yh4[a][p] = __byte_perm(q0, q1, 0x7632);
                float g0 = y0 - __uint_as_float(q0 & 0xFFFF0000u);
                float g1 = y1 - __uint_as_float(q1 & 0xFFFF0000u);
                yl4[a][p] = pack_bf16x2(g1, g0);
            }
        }
        int off = f * ROWBYTES + (((h * 2 + c) ^ fs) << 4);
        *reinterpret_cast<uint4*>(sm + 10 * BUFBYTES + off) = *reinterpret_cast<uint4*>(xh4);
        *reinterpret_cast<uint4*>(sm + 11 * BUFBYTES + off) = *reinterpret_cast<uint4*>(xl4);
        #pragma unroll
        for (int a = 0; a < 5; a++) {
            *reinterpret_cast<uint4*>(sm + (2 * a + 0) * BUFBYTES + off) = *reinterpret_cast<uint4*>(yh4[a]);
            *reinterpret_cast<uint4*>(sm + (2 * a + 1) * BUFBYTES + off) = *reinterpret_cast<uint4*>(yl4[a]);
        }
    }
    __syncthreads();

    // ====== mainloop: flattened 25 (tile,head) steps, B-frags prefetched =====
    const int lane = t & 31;
    const int w    = t >> 5;
    const int lg = lane >> 3, lr = lane & 7;
    const int ls = (lr >> 1) & 3;

    const uint32_t a_row   = (uint32_t)(((lg & 1) * 8 + lr) * ROWBYTES);
    const uint32_t a_csel0 = (uint32_t)((((lg >> 1)    ) ^ ls) << 4);   // e 0..15
    const uint32_t a_csel1 = (uint32_t)((((lg >> 1) | 2) ^ ls) << 4);   // e 16..31
    const uint32_t b_off   = (uint32_t)((lr * ROWBYTES) + ((lg ^ ls) << 4));

    uint32_t smb = (uint32_t)__cvta_generic_to_shared(sm);
    const uint32_t xh0 = smb + 10 * BUFBYTES + a_row + a_csel0;
    const uint32_t xh1 = smb + 10 * BUFBYTES + a_row + a_csel1;
    const uint32_t xl0 = smb + 11 * BUFBYTES + a_row + a_csel0;
    const uint32_t xl1 = smb + 11 * BUFBYTES + a_row + a_csel1;
    const uint32_t b_base = smb + b_off;

    // bias folded into relu threshold; log2e folded into h -> exp2;
    // constant sum(b*h) cancels under the softmax ratio.
    const float nb[4] = { -attn_b[0], -attn_b[1], -attn_b[2], -attn_b[3] };
    const float L2E = 1.4426950408889634f;
    const float ha[4] = { attn_h[0] * L2E, attn_h[1] * L2E,
                          attn_h[2] * L2E, attn_h[3] * L2E };

    const int TI4[4][5] = {{0,0,0,0,0},{0,0,0,1,1},{1,1,1,1,2},{2,2,2,3,3}};
    const int TJ4[4][5] = {{0,1,2,3,4},{5,6,7,2,3},{4,5,6,7,4},{5,6,7,6,7}};
    const int DIAGMASK[4] = { 0x03, 0x18, 0x10, 0x19 };   // diagonal-touching tiles

    const int ir0 = (lane >> 2);
    const int jc0 = 2 * (lane & 3);
    const int dmask = DIAGMASK[w];

    uint32_t ah0[4], ah1[4], al0[4], al1[4];
    int prev_ti = -1;

    float ose = 0.f, osq = 0.f;
    float tsc[4], qv[4];

    uint32_t B0[8], B1[8];

    // prefetch step 0 (tile 0, head 0)
    {
        const uint32_t brow = b_base + (uint32_t)(TJ4[w][0] * 8 * ROWBYTES);
        ldsm4(B0,     brow);
        ldsm4(B0 + 4, brow + BUFBYTES);
    }

    #pragma unroll
    for (int s = 0; s < 25; s++) {
        const int k = s / 5, a = s % 5;
        const int ti = TI4[w][k], tj = TJ4[w][k];

        // A-frag reload at tile starts (runtime ti-change check)
        if (a == 0 && ti != prev_ti) {
            const uint32_t tio = (uint32_t)(ti * 16 * ROWBYTES);
            ldsm4(ah0, xh0 + tio);
            ldsm4(ah1, xh1 + tio);
            ldsm4(al0, xl0 + tio);
            ldsm4(al1, xl1 + tio);
            prev_ti = ti;
        }

        uint32_t* cur = (s & 1) ? B1 : B0;
        uint32_t* nxt = (s & 1) ? B0 : B1;

        // prefetch next step's B-fragments (hidden behind this step's MMAs)
        if (s < 24) {
            const int kn = (s + 1) / 5, an = (s + 1) % 5;
            const uint32_t brown = b_base + (uint32_t)(TJ4[w][kn] * 8 * ROWBYTES);
            ldsm4(nxt,     brown + (uint32_t)((2 * an + 0) * BUFBYTES));
            ldsm4(nxt + 4, brown + (uint32_t)((2 * an + 1) * BUFBYTES));
        }

        // 6 MMAs: xh·yh (k0,k1), xh·yl (k0,k1), xl·yh (k0,k1)
        float d[4];
        mma16816_zc(d, ah0, cur[0], cur[1]);
        mma16816(d, ah1, cur[2], cur[3]);
        mma16816(d, ah0, cur[4], cur[5]);
        mma16816(d, ah1, cur[6], cur[7]);
        mma16816(d, al0, cur[0], cur[1]);
        mma16816(d, al1, cur[2], cur[3]);

        if (a == 0) {
            #pragma unroll
            for (int cc = 0; cc < 4; cc++) tsc[cc] = fmaxf(d[cc], nb[0]) * ha[0];
        } else if (a < 4) {
            #pragma unroll
            for (int cc = 0; cc < 4; cc++) tsc[cc] += fmaxf(d[cc], nb[a]) * ha[a];
        } else {
            #pragma unroll
            for (int cc = 0; cc < 4; cc++) qv[cc] = d[cc];

            // tile epilogue: diagonal mask (warp-uniform) + exp2 + accumulate
            if ((dmask >> k) & 1) {
                const int ib = ti * 16 + ir0, jb = tj * 8 + jc0;
                #pragma unroll
                for (int cc = 0; cc < 4; cc++) {
                    int i = ib + ((cc >= 2) ? 8 : 0);
                    int j = jb + (cc & 1);
                    if (i >= j) tsc[cc] = -1e30f;
                }
            }
            float e0 = ex2f(tsc[0]), e1 = ex2f(tsc[1]);
            float e2 = ex2f(tsc[2]), e3 = ex2f(tsc[3]);
            ose += (e0 + e1) + (e2 + e3);
            osq += (e0 * qv[0] + e1 * qv[1]) + (e2 * qv[2] + e3 * qv[3]);
        }
    }

    // ================= reduce: plain sums ====================================
    #pragma unroll
    for (int o = 16; o; o >>= 1) {
        ose += __shfl_xor_sync(0xffffffffu, ose, o);
        osq += __shfl_xor_sync(0xffffffffu, osq, o);
    }
    if (lane == 0) { rse[w] = ose; rsq[w] = osq; }
    __syncthreads();
    if (t == 0) {
        float S = rse[0] + rse[1] + rse[2] + rse[3];
        float Q = rsq[0] + rsq[1] + rsq[2] + rsq[3];
        out[b] = Q / S + pool_b[0];
    }
}

extern "C" void kernel_launch(void* const* d_in, const int* in_sizes, int n_in,
                              void* d_out, int out_size)
{
    const float* x      = (const float*)d_in[0];
    const float* attn_w = (const float*)d_in[1];
    const float* attn_b = (const float*)d_in[2];
    const float* attn_h = (const float*)d_in[3];
    const float* pool_w = (const float*)d_in[4];
    const float* pool_b = (const float*)d_in[5];
    float* out = (float*)d_out;

    cudaFuncSetAttribute(afm_kernel, cudaFuncAttributeMaxDynamicSharedMemorySize, SMEM_BYTES);

    int B = in_sizes[0] / (FDIM * EDIM);
    afm_kernel<<<B, THREADS, SMEM_BYTES>>>(x, attn_w, attn_b, attn_h, pool_w, pool_b, out);
}